// round 11
// baseline (speedup 1.0000x reference)
#include <cuda_runtime.h>
#include <cuda_fp16.h>
#include <math.h>
#include <stdint.h>

// Problem constants
#define NB 4
#define LSEQ 1024
#define EMB 1024
#define NH 32
#define HD 32

// Scratch: fp16, MMA-fragment-major layouts.
//  g_qh  : A-frag  [nh][m16(64)][kk(2)][lane(32)][4 regs = 8 half]  (Q pre-scaled by log2e/32)
//  g_kh  : B-frag  [nh][kc(32)][kk(2, d-k16)][nt(4, s-grp)][lane(32)][2 regs]
//  g_vh  : B-frag  [nh][kc(32)][kk(2, s-k16)][nt(4, d-grp)][lane(32)][2 regs]
//  g_ctxh: A-frag  [rowtile(256)][kk(64)][lane(32)][4 regs]
//  g_woh : B-frag  [ntile(128)][kk(64)][lane(32)][2 regs]
__device__ __align__(16) __half g_qh [NB * NH * LSEQ * HD];
__device__ __align__(16) __half g_kh [NB * NH * LSEQ * HD];
__device__ __align__(16) __half g_vh [NB * NH * LSEQ * HD];
__device__ __align__(16) __half g_ctxh[NB * LSEQ * EMB];
__device__ __align__(16) __half g_woh[EMB * EMB];

// ---------------------------------------------------------------------------
// helpers
// ---------------------------------------------------------------------------
__device__ __forceinline__ uint32_t smem_u32(const void* p) {
    return (uint32_t)__cvta_generic_to_shared(p);
}
__device__ __forceinline__ void ldm4(uint4& d, uint32_t a) {
    asm volatile("ldmatrix.sync.aligned.m8n8.x4.shared.b16 {%0,%1,%2,%3},[%4];"
                 : "=r"(d.x), "=r"(d.y), "=r"(d.z), "=r"(d.w) : "r"(a));
}
__device__ __forceinline__ uint32_t movm(uint32_t a) {
    uint32_t d;
    asm volatile("movmatrix.sync.aligned.m8n8.trans.b16 %0,%1;" : "=r"(d) : "r"(a));
    return d;
}
__device__ __forceinline__ uint32_t ex2h2(uint32_t a) {
    uint32_t d;
    asm volatile("ex2.approx.f16x2 %0,%1;" : "=r"(d) : "r"(a));
    return d;
}
__device__ __forceinline__ uint32_t h2u(__half2 h) { return *(uint32_t*)&h; }
__device__ __forceinline__ __half2 u2h(uint32_t u) { return *(__half2*)&u; }

// fp16 m16n8k16, fp32 accumulate
__device__ __forceinline__ void mma16(float c[4],
                                      uint32_t a0, uint32_t a1, uint32_t a2, uint32_t a3,
                                      uint32_t b0, uint32_t b1) {
    asm volatile(
        "mma.sync.aligned.m16n8k16.row.col.f32.f16.f16.f32 "
        "{%0,%1,%2,%3},{%4,%5,%6,%7},{%8,%9},{%0,%1,%2,%3};\n"
        : "+f"(c[0]), "+f"(c[1]), "+f"(c[2]), "+f"(c[3])
        : "r"(a0), "r"(a1), "r"(a2), "r"(a3), "r"(b0), "r"(b1));
}

__device__ __forceinline__ void cpa16(void* smem, const void* gmem) {
    uint32_t s = smem_u32(smem);
    asm volatile("cp.async.cg.shared.global [%0], [%1], 16;\n" :: "r"(s), "l"(gmem));
}
#define CPA_COMMIT() asm volatile("cp.async.commit_group;\n")
#define CPA_WAIT1()  asm volatile("cp.async.wait_group 1;\n")

#define GDC_LAUNCH_DEP() asm volatile("griddepcontrol.launch_dependents;")
#define GDC_WAIT()       asm volatile("griddepcontrol.wait;" ::: "memory")

// ---------------------------------------------------------------------------
// Kernel 1: per-(n,h) projection, fp16 mma, register-direct frag epilogues.
// ---------------------------------------------------------------------------
__global__ __launch_bounds__(128, 4)
void proj_mma(const float* __restrict__ xq, const float* __restrict__ xk,
              const float* __restrict__ xv,
              const float* __restrict__ Wq, const float* __restrict__ Wk,
              const float* __restrict__ Wv)
{
    __shared__ __half Xs[128][40];
    __shared__ __half Ws[32][40];

    GDC_LAUNCH_DEP();

    int t = threadIdx.x, lane = t & 31, warp = t >> 5;
    int g = lane >> 2, tig = lane & 3;
    int nh = blockIdx.x, n = nh >> 5, h = nh & 31;
    int lt = blockIdx.y, p = blockIdx.z;

    const float* x = (p == 0) ? xq : (p == 1) ? xk : xv;
    const float* W = (p == 0) ? Wq : (p == 1) ? Wk : Wv;
    const float* xrow = x + ((size_t)(n * 1024 + lt * 128)) * 1024 + h * 32;

#pragma unroll
    for (int i = t; i < 1024; i += 128) {
        int r = i >> 3, c4 = (i & 7) * 4;
        float4 v = *(const float4*)&xrow[(size_t)r * 1024 + c4];
        ((__half2*)&Xs[r][c4])[0] = __floats2half2_rn(v.x, v.y);
        ((__half2*)&Xs[r][c4])[1] = __floats2half2_rn(v.z, v.w);
    }
#pragma unroll
    for (int i = t; i < 1024; i += 128)
        Ws[i >> 5][i & 31] = __float2half_rn(W[i]);
    __syncthreads();

    uint32_t bf[4][2][2];
#pragma unroll
    for (int nt = 0; nt < 4; nt++)
#pragma unroll
        for (int kk = 0; kk < 2; kk++) {
            bf[nt][kk][0] = *(const uint32_t*)&Ws[nt * 8 + g][kk * 16 + 2 * tig];
            bf[nt][kk][1] = *(const uint32_t*)&Ws[nt * 8 + g][kk * 16 + 2 * tig + 8];
        }

    uint4 av[2][2];
    int arow = warp * 32 + (lane & 7) + ((lane >> 3) & 1) * 8;
    int acol = (lane >> 4) * 8;
#pragma unroll
    for (int mt = 0; mt < 2; mt++)
#pragma unroll
        for (int kk = 0; kk < 2; kk++)
            ldm4(av[mt][kk], smem_u32(&Xs[arow + mt * 16][acol + kk * 16]));

    float cf[2][4][4];
#pragma unroll
    for (int mt = 0; mt < 2; mt++)
#pragma unroll
        for (int nt = 0; nt < 4; nt++)
#pragma unroll
            for (int r = 0; r < 4; r++) cf[mt][nt][r] = 0.f;

#pragma unroll
    for (int kk = 0; kk < 2; kk++)
#pragma unroll
        for (int nt = 0; nt < 4; nt++)
#pragma unroll
            for (int mt = 0; mt < 2; mt++)
                mma16(cf[mt][nt], av[mt][kk].x, av[mt][kk].y, av[mt][kk].z, av[mt][kk].w,
                      bf[nt][kk][0], bf[nt][kk][1]);

    const float SQ = 0.03125f * 1.44269504f;   // log2e / sqrt(E)
    float sc = (p == 0) ? SQ : 1.f;
    uint32_t hh[2][4][2];
#pragma unroll
    for (int mt = 0; mt < 2; mt++)
#pragma unroll
        for (int nt = 0; nt < 4; nt++) {
            hh[mt][nt][0] = h2u(__floats2half2_rn(cf[mt][nt][0] * sc, cf[mt][nt][1] * sc));
            hh[mt][nt][1] = h2u(__floats2half2_rn(cf[mt][nt][2] * sc, cf[mt][nt][3] * sc));
        }

#pragma unroll
    for (int mt = 0; mt < 2; mt++) {
        int m16 = lt * 8 + warp * 2 + mt;
        if (p == 0) {                           // Q: A-frag-major
#pragma unroll
            for (int kk = 0; kk < 2; kk++) {
                uint4 u;
                u.x = hh[mt][2 * kk][0];
                u.y = hh[mt][2 * kk][1];
                u.z = hh[mt][2 * kk + 1][0];
                u.w = hh[mt][2 * kk + 1][1];
                ((uint4*)g_qh)[((nh * 64 + m16) * 2 + kk) * 32 + lane] = u;
            }
        } else if (p == 1) {                    // K: B-frag-major
            int kc = m16 >> 1, ntk = (m16 & 1) * 2;
#pragma unroll
            for (int kk = 0; kk < 2; kk++) {
                uint2 u0, u1;
                u0.x = hh[mt][2 * kk][0];     u0.y = hh[mt][2 * kk + 1][0];
                u1.x = hh[mt][2 * kk][1];     u1.y = hh[mt][2 * kk + 1][1];
                ((uint2*)g_kh)[(((nh * 32 + kc) * 2 + kk) * 4 + ntk)     * 32 + lane] = u0;
                ((uint2*)g_kh)[(((nh * 32 + kc) * 2 + kk) * 4 + ntk + 1) * 32 + lane] = u1;
            }
        } else {                                // V: movmatrix transpose
            int kc = m16 >> 1, kkv = m16 & 1;
#pragma unroll
            for (int nt = 0; nt < 4; nt++) {
                uint2 u;
                u.x = movm(hh[mt][nt][0]);
                u.y = movm(hh[mt][nt][1]);
                ((uint2*)g_vh)[(((nh * 32 + kc) * 2 + kkv) * 4 + nt) * 32 + lane] = u;
            }
        }
    }
}

// ---------------------------------------------------------------------------
// Kernel 1b: Wo -> fp16 B-frag-major g_woh (PSS: overlaps proj).
// ---------------------------------------------------------------------------
__global__ void round_wo(const float* __restrict__ Wo)
{
    int idx = (blockIdx.x * 256 + threadIdx.x) * 4;
    int j = idx >> 10, k0 = idx & 1023;
    float4 v = *(const float4*)&Wo[j * 1024 + k0];
    int ntile = j >> 3, gj = j & 7;
#pragma unroll
    for (int q = 0; q < 4; q += 2) {
        int k = k0 + q;
        int kk = k >> 4, reg = (k >> 3) & 1, tig2 = (k & 7) >> 1;
        int hidx = ((ntile * 64 + kk) * 32 + gj * 4 + tig2) * 2 + reg;
        ((__half2*)g_woh)[hidx] =
            __floats2half2_rn(q ? v.z : v.x, q ? v.w : v.y);
    }
}

// ---------------------------------------------------------------------------
// Kernel 2: flash attention. 256 query rows/CTA, 4 warps x 64 rows (mt=4:
// K/V frag reads amortized to 64B/mma). 64-key chunks, 3-stage ring,
// HADD2-tree l.
// ---------------------------------------------------------------------------
#define BM 128

__global__ __launch_bounds__(BM)
void attn_mma(const int* __restrict__ mask)
{
    __shared__ __align__(16) __half Ksm[3][2048];   // 64 keys x 32 d per stage
    __shared__ __align__(16) __half Vsm[3][2048];
    __shared__ float Msf[LSEQ];
    __shared__ int   s_allones;

    int nh = blockIdx.x;
    int n  = nh >> 5;
    int h  = nh & 31;
    int qy = blockIdx.y;                 // 256-row tile (4 per nh)

    const __half* kf = g_kh + nh * 32768;
    const __half* vf = g_vh + nh * 32768;
    const int*    mb = mask + n * LSEQ;

    int t = threadIdx.x;
    int lane = t & 31, warp = t >> 5;
    int tigL = lane & 3;

    if (t == 0) s_allones = 1;

#pragma unroll
    for (int st = 0; st < 2; st++) {
        cpa16(&Ksm[st][t * 8],        kf + st * 2048 + t * 8);
        cpa16(&Ksm[st][1024 + t * 8], kf + st * 2048 + 1024 + t * 8);
        cpa16(&Vsm[st][t * 8],        vf + st * 2048 + t * 8);
        cpa16(&Vsm[st][1024 + t * 8], vf + st * 2048 + 1024 + t * 8);
        CPA_COMMIT();
    }
    __syncthreads();

    for (int i = t; i < LSEQ; i += BM) {
        int m = mb[i];
        Msf[i] = m ? 0.f : -1e20f;
        if (!m) s_allones = 0;
    }

    // Q fragments: 4 m16-tiles per warp (m16 = qy*16 + warp*4 + mt)
    uint4 qv[4][2];
#pragma unroll
    for (int mt = 0; mt < 4; mt++)
#pragma unroll
        for (int kk = 0; kk < 2; kk++)
            qv[mt][kk] = ((const uint4*)g_qh)
                [(((nh * 64 + qy * 16 + warp * 4 + mt) * 2 + kk) * 32 + lane)];

    float of[4][4][4];
#pragma unroll
    for (int mt = 0; mt < 4; mt++)
#pragma unroll
        for (int nt = 0; nt < 4; nt++)
#pragma unroll
            for (int r = 0; r < 4; r++) of[mt][nt][r] = 0.f;
    float lst[4][2];
#pragma unroll
    for (int mt = 0; mt < 4; mt++) { lst[mt][0] = 0.f; lst[mt][1] = 0.f; }

    __syncthreads();
    int allones = s_allones;

#pragma unroll 1
    for (int c = 0; c < LSEQ / 64; c++) {
        CPA_WAIT1();
        __syncthreads();
        if (c + 2 < LSEQ / 64) {
            int sl = (c + 2) % 3;
            const __half* kn = kf + (c + 2) * 2048;
            const __half* vn = vf + (c + 2) * 2048;
            cpa16(&Ksm[sl][t * 8],        kn + t * 8);
            cpa16(&Ksm[sl][1024 + t * 8], kn + 1024 + t * 8);
            cpa16(&Vsm[sl][t * 8],        vn + t * 8);
            cpa16(&Vsm[sl][1024 + t * 8], vn + 1024 + t * 8);
        }
        CPA_COMMIT();
        int b = c % 3;

#pragma unroll
        for (int sub = 0; sub < 2; sub++) {
            int base = sub * 1024;

            // ---- S = Q K^T ----
            float sf[4][4][4];
#pragma unroll
            for (int mt = 0; mt < 4; mt++)
#pragma unroll
                for (int nt = 0; nt < 4; nt++)
#pragma unroll
                    for (int r = 0; r < 4; r++) sf[mt][nt][r] = 0.f;

#pragma unroll
            for (int kk = 0; kk < 2; kk++)
#pragma unroll
                for (int nt = 0; nt < 4; nt++) {
                    uint2 kb = *(const uint2*)&Ksm[b][base + ((kk * 4 + nt) * 32 + lane) * 4];
#pragma unroll
                    for (int mt = 0; mt < 4; mt++)
                        mma16(sf[mt][nt],
                              qv[mt][kk].x, qv[mt][kk].y, qv[mt][kk].z, qv[mt][kk].w,
                              kb.x, kb.y);
                }

            // ---- P = 2^S -> A-frag registers ----
            int ktb = c * 64 + sub * 32;
            uint32_t pf[4][2][4];
#pragma unroll
            for (int mt = 0; mt < 4; mt++)
#pragma unroll
                for (int nt = 0; nt < 4; nt++) {
                    float s0 = sf[mt][nt][0], s1 = sf[mt][nt][1];
                    float s2 = sf[mt][nt][2], s3 = sf[mt][nt][3];
                    if (!allones) {
                        int col = ktb + nt * 8 + 2 * tigL;
                        float b0m = Msf[col], b1m = Msf[col + 1];
                        s0 += b0m; s1 += b1m; s2 += b0m; s3 += b1m;
                    }
                    pf[mt][nt >> 1][(nt & 1) * 2 + 0] = ex2h2(h2u(__floats2half2_rn(s0, s1)));
                    pf[mt][nt >> 1][(nt & 1) * 2 + 1] = ex2h2(h2u(__floats2half2_rn(s2, s3)));
                }

            // ---- l partials via HADD2 tree (off the tensor pipe) ----
#pragma unroll
            for (int mt = 0; mt < 4; mt++) {
                __half2 s0 = __hadd2(__hadd2(u2h(pf[mt][0][0]), u2h(pf[mt][0][2])),
                                     __hadd2(u2h(pf[mt][1][0]), u2h(pf[mt][1][2])));
                __half2 s1 = __hadd2(__hadd2(u2h(pf[mt][0][1]), u2h(pf[mt][0][3])),
                                     __hadd2(u2h(pf[mt][1][1]), u2h(pf[mt][1][3])));
                float2 f0 = __half22float2(s0);
                float2 f1 = __half22float2(s1);
                lst[mt][0] += f0.x + f0.y;
                lst[mt][1] += f1.x + f1.y;
            }

            // ---- O += P V ----
#pragma unroll
            for (int kk = 0; kk < 2; kk++)
#pragma unroll
                for (int nt = 0; nt < 4; nt++) {
                    uint2 vb = *(const uint2*)&Vsm[b][base + ((kk * 4 + nt) * 32 + lane) * 4];
#pragma unroll
                    for (int mt = 0; mt < 4; mt++)
                        mma16(of[mt][nt],
                              pf[mt][kk][0], pf[mt][kk][1], pf[mt][kk][2], pf[mt][kk][3],
                              vb.x, vb.y);
                }
        }
    }

    // ---- finalize: quad-reduce l, scale, write ctx A-frag-major ----
#pragma unroll
    for (int mt = 0; mt < 4; mt++) {
        float l0 = lst[mt][0], l1 = lst[mt][1];
        l0 += __shfl_xor_sync(0xffffffffu, l0, 1);
        l0 += __shfl_xor_sync(0xffffffffu, l0, 2);
        l1 += __shfl_xor_sync(0xffffffffu, l1, 1);
        l1 += __shfl_xor_sync(0xffffffffu, l1, 2);
        float inv0 = 1.f / l0, inv1 = 1.f / l1;

        int rowtile = n * 64 + qy * 16 + warp * 4 + mt;
#pragma unroll
        for (int nt = 0; nt < 4; nt++) {
            int kk = h * 2 + (nt >> 1);
            uint2 w;
            w.x = h2u(__floats2half2_rn(of[mt][nt][0] * inv0, of[mt][nt][1] * inv0));
            w.y = h2u(__floats2half2_rn(of[mt][nt][2] * inv1, of[mt][nt][3] * inv1));
            ((uint2*)g_ctxh)[((rowtile * 64 + kk) * 32 + lane) * 2 + (nt & 1)] = w;
        }
    }
}

// ---------------------------------------------------------------------------
// Kernel 3: out = ctx @ Wo^T + bo. CTA tile 128x128, 4 warps x (64x64) tiles
// -> 128B smem/mma (half of before). 3-stage ring, 128 threads.
// ---------------------------------------------------------------------------
__global__ __launch_bounds__(128)
void out_gemm_mma(const float* __restrict__ bo, float* __restrict__ out)
{
    __shared__ __align__(16) __half Asm[3][4096];    // 128 rows x 32 k / stage
    __shared__ __align__(16) __half Bsm[3][4096];    // 128 cols x 32 k / stage

    GDC_WAIT();

    int t = threadIdx.x;
    int lane = t & 31, warp = t >> 5;
    int g = lane >> 2, tigL = lane & 3;
    int rb = blockIdx.y, jb = blockIdx.x;
    int wr = warp >> 1, wc = warp & 1;   // 2x2 warps of 64x64

    float cf[4][8][4];
#pragma unroll
    for (int mt = 0; mt < 4; mt++)
#pragma unroll
        for (int nt = 0; nt < 8; nt++)
#pragma unroll
            for (int r = 0; r < 4; r++) cf[mt][nt][r] = 0.f;

#define STAGE(st, kc)                                                          \
    _Pragma("unroll")                                                          \
    for (int i = t; i < 512; i += 128) {                                       \
        int rt = i >> 6, kkl = (i >> 5) & 1, ln = i & 31;                      \
        cpa16(&Asm[st][i * 8],                                                 \
              g_ctxh + (((rb * 8 + rt) * 64 + (kc) * 2 + kkl) * 32 + ln) * 8); \
    }                                                                          \
    _Pragma("unroll")                                                          \
    for (int i = t; i < 512; i += 128) {                                       \
        int nt = i >> 5, kkb = (i >> 4) & 1, lp = i & 15;                      \
        cpa16(&Bsm[st][i * 8],                                                 \
              g_woh + (((jb * 16 + nt) * 64 + (kc) * 2 + kkb) * 32 + lp * 2) * 4); \
    }

    STAGE(0, 0); CPA_COMMIT();
    STAGE(1, 1); CPA_COMMIT();

#pragma unroll 1
    for (int c = 0; c < 32; c++) {
        CPA_WAIT1();
        __syncthreads();
        if (c + 2 < 32) { STAGE((c + 2) % 3, c + 2); }
        CPA_COMMIT();
        int b = c % 3;

#pragma unroll
        for (int kkl = 0; kkl < 2; kkl++) {
            uint4 av[4];
#pragma unroll
            for (int mt = 0; mt < 4; mt++)
                av[mt] = *(const uint4*)&Asm[b][(((wr * 4 + mt) * 2 + kkl) * 32 + lane) * 8];
#pragma unroll
            for (int nt = 0; nt < 8; nt++) {
                uint2 bv = *(const uint2*)&Bsm[b][(((wc * 8 + nt) * 2 + kkl) * 32 + lane) * 4];
#pragma unroll
                for (int mt = 0; mt < 4; mt++)
                    mma16(cf[mt][nt], av[mt].x, av[mt].y, av[mt].z, av[mt].w,
                          bv.x, bv.y);
            }
        }
    }

#pragma unroll
    for (int mt = 0; mt < 4; mt++) {
        int row = rb * 128 + wr * 64 + mt * 16 + g;
#pragma unroll
        for (int nt = 0; nt < 8; nt++) {
            int col = jb * 128 + wc * 64 + nt * 8 + 2 * tigL;
            float b0 = bo[col], b1 = bo[col + 1];
            float2 w0 = make_float2(cf[mt][nt][0] + b0, cf[mt][nt][1] + b1);
            float2 w1 = make_float2(cf[mt][nt][2] + b0, cf[mt][nt][3] + b1);
            *(float2*)&out[row * EMB + col]       = w0;
            *(float2*)&out[(row + 8) * EMB + col] = w1;
        }
    }
}

// ---------------------------------------------------------------------------
extern "C" void kernel_launch(void* const* d_in, const int* in_sizes, int n_in,
                              void* d_out, int out_size)
{
    const float* values = (const float*)d_in[0];
    const float* keys   = (const float*)d_in[1];
    const float* query  = (const float*)d_in[2];
    const int*   mask   = (const int*)d_in[3];
    const float* Wv     = (const float*)d_in[4];
    const float* Wk     = (const float*)d_in[5];
    const float* Wq     = (const float*)d_in[6];
    const float* Wo     = (const float*)d_in[7];
    const float* bo     = (const float*)d_in[8];
    float* out = (float*)d_out;

    // 1) projections (triggers dependents immediately)
    dim3 pgrid(NB * NH, LSEQ / 128, 3);
    proj_mma<<<pgrid, 128>>>(query, keys, values, Wq, Wk, Wv);

    // 2) round_wo: PSS -> overlaps proj (reads only harness input Wo)
    {
        cudaLaunchConfig_t cfg = {};
        cfg.gridDim  = dim3(EMB * EMB / 1024);
        cfg.blockDim = dim3(256);
        cudaLaunchAttribute at[1];
        at[0].id = cudaLaunchAttributeProgrammaticStreamSerialization;
        at[0].val.programmaticStreamSerializationAllowed = 1;
        cfg.attrs = at;
        cfg.numAttrs = 1;
        cudaLaunchKernelEx(&cfg, round_wo, Wo);
    }

    // 3) attention: normal launch; 256 query rows per CTA
    dim3 agrid(NB * NH, LSEQ / 256);
    attn_mma<<<agrid, BM>>>(mask);

    // 4) output GEMM: PSS + device-side griddepcontrol.wait
    {
        cudaLaunchConfig_t cfg = {};
        cfg.gridDim  = dim3(EMB / 128, (NB * LSEQ) / 128);
        cfg.blockDim = dim3(128);
        cudaLaunchAttribute at[1];
        at[0].id = cudaLaunchAttributeProgrammaticStreamSerialization;
        at[0].val.programmaticStreamSerializationAllowed = 1;
        cfg.attrs = at;
        cfg.numAttrs = 1;
        cudaLaunchKernelEx(&cfg, out_gemm_mma, bo, out);
    }
}

// round 12
// speedup vs baseline: 1.0880x; 1.0880x over previous
#include <cuda_runtime.h>
#include <cuda_fp16.h>
#include <math.h>
#include <stdint.h>

// Problem constants
#define NB 4
#define LSEQ 1024
#define EMB 1024
#define NH 32
#define HD 32

// Scratch: fp16, MMA-fragment-major layouts.
//  g_qh  : A-frag  [nh][m16(64)][kk(2)][lane(32)][4 regs = 8 half]  (Q pre-scaled by log2e/32)
//  g_kh  : B-frag  [nh][kc(32)][kk(2, d-k16)][nt(4, s-grp)][lane(32)][2 regs]
//  g_vh  : B-frag  [nh][kc(32)][kk(2, s-k16)][nt(4, d-grp)][lane(32)][2 regs]
//  g_ctxh: A-frag  [rowtile(256)][kk(64)][lane(32)][4 regs]
//  g_woh : B-frag  [ntile(128)][kk(64)][lane(32)][2 regs]
__device__ __align__(16) __half g_qh [NB * NH * LSEQ * HD];
__device__ __align__(16) __half g_kh [NB * NH * LSEQ * HD];
__device__ __align__(16) __half g_vh [NB * NH * LSEQ * HD];
__device__ __align__(16) __half g_ctxh[NB * LSEQ * EMB];
__device__ __align__(16) __half g_woh[EMB * EMB];

// ---------------------------------------------------------------------------
// helpers
// ---------------------------------------------------------------------------
__device__ __forceinline__ uint32_t smem_u32(const void* p) {
    return (uint32_t)__cvta_generic_to_shared(p);
}
__device__ __forceinline__ void ldm4(uint4& d, uint32_t a) {
    asm volatile("ldmatrix.sync.aligned.m8n8.x4.shared.b16 {%0,%1,%2,%3},[%4];"
                 : "=r"(d.x), "=r"(d.y), "=r"(d.z), "=r"(d.w) : "r"(a));
}
__device__ __forceinline__ uint32_t movm(uint32_t a) {
    uint32_t d;
    asm volatile("movmatrix.sync.aligned.m8n8.trans.b16 %0,%1;" : "=r"(d) : "r"(a));
    return d;
}
__device__ __forceinline__ uint32_t ex2h2(uint32_t a) {
    uint32_t d;
    asm volatile("ex2.approx.f16x2 %0,%1;" : "=r"(d) : "r"(a));
    return d;
}
__device__ __forceinline__ uint32_t h2u(__half2 h) { return *(uint32_t*)&h; }
__device__ __forceinline__ __half2 u2h(uint32_t u) { return *(__half2*)&u; }

// fp16 m16n8k16, fp32 accumulate
__device__ __forceinline__ void mma16(float c[4],
                                      uint32_t a0, uint32_t a1, uint32_t a2, uint32_t a3,
                                      uint32_t b0, uint32_t b1) {
    asm volatile(
        "mma.sync.aligned.m16n8k16.row.col.f32.f16.f16.f32 "
        "{%0,%1,%2,%3},{%4,%5,%6,%7},{%8,%9},{%0,%1,%2,%3};\n"
        : "+f"(c[0]), "+f"(c[1]), "+f"(c[2]), "+f"(c[3])
        : "r"(a0), "r"(a1), "r"(a2), "r"(a3), "r"(b0), "r"(b1));
}

__device__ __forceinline__ void cpa16(void* smem, const void* gmem) {
    uint32_t s = smem_u32(smem);
    asm volatile("cp.async.cg.shared.global [%0], [%1], 16;\n" :: "r"(s), "l"(gmem));
}
#define CPA_COMMIT() asm volatile("cp.async.commit_group;\n")
#define CPA_WAIT1()  asm volatile("cp.async.wait_group 1;\n")

#define GDC_LAUNCH_DEP() asm volatile("griddepcontrol.launch_dependents;")
#define GDC_WAIT()       asm volatile("griddepcontrol.wait;" ::: "memory")

// ---------------------------------------------------------------------------
// Kernel 1: per-(n,h) projection, fp16 mma, register-direct frag epilogues.
// ---------------------------------------------------------------------------
__global__ __launch_bounds__(128, 4)
void proj_mma(const float* __restrict__ xq, const float* __restrict__ xk,
              const float* __restrict__ xv,
              const float* __restrict__ Wq, const float* __restrict__ Wk,
              const float* __restrict__ Wv)
{
    __shared__ __half Xs[128][40];
    __shared__ __half Ws[32][40];

    GDC_LAUNCH_DEP();

    int t = threadIdx.x, lane = t & 31, warp = t >> 5;
    int g = lane >> 2, tig = lane & 3;
    int nh = blockIdx.x, n = nh >> 5, h = nh & 31;
    int lt = blockIdx.y, p = blockIdx.z;

    const float* x = (p == 0) ? xq : (p == 1) ? xk : xv;
    const float* W = (p == 0) ? Wq : (p == 1) ? Wk : Wv;
    const float* xrow = x + ((size_t)(n * 1024 + lt * 128)) * 1024 + h * 32;

#pragma unroll
    for (int i = t; i < 1024; i += 128) {
        int r = i >> 3, c4 = (i & 7) * 4;
        float4 v = *(const float4*)&xrow[(size_t)r * 1024 + c4];
        ((__half2*)&Xs[r][c4])[0] = __floats2half2_rn(v.x, v.y);
        ((__half2*)&Xs[r][c4])[1] = __floats2half2_rn(v.z, v.w);
    }
#pragma unroll
    for (int i = t; i < 1024; i += 128)
        Ws[i >> 5][i & 31] = __float2half_rn(W[i]);
    __syncthreads();

    uint32_t bf[4][2][2];
#pragma unroll
    for (int nt = 0; nt < 4; nt++)
#pragma unroll
        for (int kk = 0; kk < 2; kk++) {
            bf[nt][kk][0] = *(const uint32_t*)&Ws[nt * 8 + g][kk * 16 + 2 * tig];
            bf[nt][kk][1] = *(const uint32_t*)&Ws[nt * 8 + g][kk * 16 + 2 * tig + 8];
        }

    uint4 av[2][2];
    int arow = warp * 32 + (lane & 7) + ((lane >> 3) & 1) * 8;
    int acol = (lane >> 4) * 8;
#pragma unroll
    for (int mt = 0; mt < 2; mt++)
#pragma unroll
        for (int kk = 0; kk < 2; kk++)
            ldm4(av[mt][kk], smem_u32(&Xs[arow + mt * 16][acol + kk * 16]));

    float cf[2][4][4];
#pragma unroll
    for (int mt = 0; mt < 2; mt++)
#pragma unroll
        for (int nt = 0; nt < 4; nt++)
#pragma unroll
            for (int r = 0; r < 4; r++) cf[mt][nt][r] = 0.f;

#pragma unroll
    for (int kk = 0; kk < 2; kk++)
#pragma unroll
        for (int nt = 0; nt < 4; nt++)
#pragma unroll
            for (int mt = 0; mt < 2; mt++)
                mma16(cf[mt][nt], av[mt][kk].x, av[mt][kk].y, av[mt][kk].z, av[mt][kk].w,
                      bf[nt][kk][0], bf[nt][kk][1]);

    const float SQ = 0.03125f * 1.44269504f;   // log2e / sqrt(E)
    float sc = (p == 0) ? SQ : 1.f;
    uint32_t hh[2][4][2];
#pragma unroll
    for (int mt = 0; mt < 2; mt++)
#pragma unroll
        for (int nt = 0; nt < 4; nt++) {
            hh[mt][nt][0] = h2u(__floats2half2_rn(cf[mt][nt][0] * sc, cf[mt][nt][1] * sc));
            hh[mt][nt][1] = h2u(__floats2half2_rn(cf[mt][nt][2] * sc, cf[mt][nt][3] * sc));
        }

#pragma unroll
    for (int mt = 0; mt < 2; mt++) {
        int m16 = lt * 8 + warp * 2 + mt;
        if (p == 0) {                           // Q: A-frag-major
#pragma unroll
            for (int kk = 0; kk < 2; kk++) {
                uint4 u;
                u.x = hh[mt][2 * kk][0];
                u.y = hh[mt][2 * kk][1];
                u.z = hh[mt][2 * kk + 1][0];
                u.w = hh[mt][2 * kk + 1][1];
                ((uint4*)g_qh)[((nh * 64 + m16) * 2 + kk) * 32 + lane] = u;
            }
        } else if (p == 1) {                    // K: B-frag-major
            int kc = m16 >> 1, ntk = (m16 & 1) * 2;
#pragma unroll
            for (int kk = 0; kk < 2; kk++) {
                uint2 u0, u1;
                u0.x = hh[mt][2 * kk][0];     u0.y = hh[mt][2 * kk + 1][0];
                u1.x = hh[mt][2 * kk][1];     u1.y = hh[mt][2 * kk + 1][1];
                ((uint2*)g_kh)[(((nh * 32 + kc) * 2 + kk) * 4 + ntk)     * 32 + lane] = u0;
                ((uint2*)g_kh)[(((nh * 32 + kc) * 2 + kk) * 4 + ntk + 1) * 32 + lane] = u1;
            }
        } else {                                // V: movmatrix transpose
            int kc = m16 >> 1, kkv = m16 & 1;
#pragma unroll
            for (int nt = 0; nt < 4; nt++) {
                uint2 u;
                u.x = movm(hh[mt][nt][0]);
                u.y = movm(hh[mt][nt][1]);
                ((uint2*)g_vh)[(((nh * 32 + kc) * 2 + kkv) * 4 + nt) * 32 + lane] = u;
            }
        }
    }
}

// ---------------------------------------------------------------------------
// Kernel 1b: Wo -> fp16 B-frag-major g_woh (PSS: overlaps proj).
// ---------------------------------------------------------------------------
__global__ void round_wo(const float* __restrict__ Wo)
{
    int idx = (blockIdx.x * 256 + threadIdx.x) * 4;
    int j = idx >> 10, k0 = idx & 1023;
    float4 v = *(const float4*)&Wo[j * 1024 + k0];
    int ntile = j >> 3, gj = j & 7;
#pragma unroll
    for (int q = 0; q < 4; q += 2) {
        int k = k0 + q;
        int kk = k >> 4, reg = (k >> 3) & 1, tig2 = (k & 7) >> 1;
        int hidx = ((ntile * 64 + kk) * 32 + gj * 4 + tig2) * 2 + reg;
        ((__half2*)g_woh)[hidx] =
            __floats2half2_rn(q ? v.z : v.x, q ? v.w : v.y);
    }
}

// ---------------------------------------------------------------------------
// Kernel 2: flash attention (R10 config: 128 rows/CTA, mt=2). 64-key chunks,
// 3-stage ring, HADD2-tree l.
// ---------------------------------------------------------------------------
#define BM 128

__global__ __launch_bounds__(BM, 4)
void attn_mma(const int* __restrict__ mask)
{
    __shared__ __align__(16) __half Ksm[3][2048];   // 64 keys x 32 d per stage
    __shared__ __align__(16) __half Vsm[3][2048];
    __shared__ float Msf[LSEQ];
    __shared__ int   s_allones;

    int nh = blockIdx.x;
    int n  = nh >> 5;
    int h  = nh & 31;
    int qy = blockIdx.y;

    const __half* kf = g_kh + nh * 32768;
    const __half* vf = g_vh + nh * 32768;
    const int*    mb = mask + n * LSEQ;

    int t = threadIdx.x;
    int lane = t & 31, warp = t >> 5;
    int tigL = lane & 3;

    if (t == 0) s_allones = 1;

#pragma unroll
    for (int st = 0; st < 2; st++) {
        cpa16(&Ksm[st][t * 8],        kf + st * 2048 + t * 8);
        cpa16(&Ksm[st][1024 + t * 8], kf + st * 2048 + 1024 + t * 8);
        cpa16(&Vsm[st][t * 8],        vf + st * 2048 + t * 8);
        cpa16(&Vsm[st][1024 + t * 8], vf + st * 2048 + 1024 + t * 8);
        CPA_COMMIT();
    }
    __syncthreads();

    for (int i = t; i < LSEQ; i += BM) {
        int m = mb[i];
        Msf[i] = m ? 0.f : -1e20f;
        if (!m) s_allones = 0;
    }

    uint4 qv[2][2];
#pragma unroll
    for (int mt = 0; mt < 2; mt++)
#pragma unroll
        for (int kk = 0; kk < 2; kk++)
            qv[mt][kk] = ((const uint4*)g_qh)
                [(((nh * 64 + qy * 8 + warp * 2 + mt) * 2 + kk) * 32 + lane)];

    float of[2][4][4];
#pragma unroll
    for (int mt = 0; mt < 2; mt++)
#pragma unroll
        for (int nt = 0; nt < 4; nt++)
#pragma unroll
            for (int r = 0; r < 4; r++) of[mt][nt][r] = 0.f;
    float lst[2][2] = {{0.f, 0.f}, {0.f, 0.f}};

    __syncthreads();
    int allones = s_allones;

#pragma unroll 1
    for (int c = 0; c < LSEQ / 64; c++) {
        CPA_WAIT1();
        __syncthreads();
        if (c + 2 < LSEQ / 64) {
            int sl = (c + 2) % 3;
            const __half* kn = kf + (c + 2) * 2048;
            const __half* vn = vf + (c + 2) * 2048;
            cpa16(&Ksm[sl][t * 8],        kn + t * 8);
            cpa16(&Ksm[sl][1024 + t * 8], kn + 1024 + t * 8);
            cpa16(&Vsm[sl][t * 8],        vn + t * 8);
            cpa16(&Vsm[sl][1024 + t * 8], vn + 1024 + t * 8);
        }
        CPA_COMMIT();
        int b = c % 3;

#pragma unroll
        for (int sub = 0; sub < 2; sub++) {
            int base = sub * 1024;

            float sf[2][4][4];
#pragma unroll
            for (int mt = 0; mt < 2; mt++)
#pragma unroll
                for (int nt = 0; nt < 4; nt++)
#pragma unroll
                    for (int r = 0; r < 4; r++) sf[mt][nt][r] = 0.f;

#pragma unroll
            for (int kk = 0; kk < 2; kk++)
#pragma unroll
                for (int nt = 0; nt < 4; nt++) {
                    uint2 kb = *(const uint2*)&Ksm[b][base + ((kk * 4 + nt) * 32 + lane) * 4];
#pragma unroll
                    for (int mt = 0; mt < 2; mt++)
                        mma16(sf[mt][nt],
                              qv[mt][kk].x, qv[mt][kk].y, qv[mt][kk].z, qv[mt][kk].w,
                              kb.x, kb.y);
                }

            int ktb = c * 64 + sub * 32;
            uint32_t pf[2][2][4];
#pragma unroll
            for (int mt = 0; mt < 2; mt++)
#pragma unroll
                for (int nt = 0; nt < 4; nt++) {
                    float s0 = sf[mt][nt][0], s1 = sf[mt][nt][1];
                    float s2 = sf[mt][nt][2], s3 = sf[mt][nt][3];
                    if (!allones) {
                        int col = ktb + nt * 8 + 2 * tigL;
                        float b0m = Msf[col], b1m = Msf[col + 1];
                        s0 += b0m; s1 += b1m; s2 += b0m; s3 += b1m;
                    }
                    pf[mt][nt >> 1][(nt & 1) * 2 + 0] = ex2h2(h2u(__floats2half2_rn(s0, s1)));
                    pf[mt][nt >> 1][(nt & 1) * 2 + 1] = ex2h2(h2u(__floats2half2_rn(s2, s3)));
                }

#pragma unroll
            for (int mt = 0; mt < 2; mt++) {
                __half2 s0 = __hadd2(__hadd2(u2h(pf[mt][0][0]), u2h(pf[mt][0][2])),
                                     __hadd2(u2h(pf[mt][1][0]), u2h(pf[mt][1][2])));
                __half2 s1 = __hadd2(__hadd2(u2h(pf[mt][0][1]), u2h(pf[mt][0][3])),
                                     __hadd2(u2h(pf[mt][1][1]), u2h(pf[mt][1][3])));
                float2 f0 = __half22float2(s0);
                float2 f1 = __half22float2(s1);
                lst[mt][0] += f0.x + f0.y;
                lst[mt][1] += f1.x + f1.y;
            }

#pragma unroll
            for (int kk = 0; kk < 2; kk++)
#pragma unroll
                for (int nt = 0; nt < 4; nt++) {
                    uint2 vb = *(const uint2*)&Vsm[b][base + ((kk * 4 + nt) * 32 + lane) * 4];
#pragma unroll
                    for (int mt = 0; mt < 2; mt++)
                        mma16(of[mt][nt],
                              pf[mt][kk][0], pf[mt][kk][1], pf[mt][kk][2], pf[mt][kk][3],
                              vb.x, vb.y);
                }
        }
    }

#pragma unroll
    for (int mt = 0; mt < 2; mt++) {
        float l0 = lst[mt][0], l1 = lst[mt][1];
        l0 += __shfl_xor_sync(0xffffffffu, l0, 1);
        l0 += __shfl_xor_sync(0xffffffffu, l0, 2);
        l1 += __shfl_xor_sync(0xffffffffu, l1, 1);
        l1 += __shfl_xor_sync(0xffffffffu, l1, 2);
        float inv0 = 1.f / l0, inv1 = 1.f / l1;

        int rowtile = n * 64 + qy * 8 + warp * 2 + mt;
#pragma unroll
        for (int nt = 0; nt < 4; nt++) {
            int kk = h * 2 + (nt >> 1);
            uint2 w;
            w.x = h2u(__floats2half2_rn(of[mt][nt][0] * inv0, of[mt][nt][1] * inv0));
            w.y = h2u(__floats2half2_rn(of[mt][nt][2] * inv1, of[mt][nt][3] * inv1));
            ((uint2*)g_ctxh)[((rowtile * 64 + kk) * 32 + lane) * 2 + (nt & 1)] = w;
        }
    }
}

// ---------------------------------------------------------------------------
// Kernel 3: out = ctx @ Wo^T + bo. 256 threads = 8 warps, CTA 128x128,
// warp tile 64x32 (192B/mma crossbar, ~14 warps/SM). 3-stage ring.
// ---------------------------------------------------------------------------
__global__ __launch_bounds__(256)
void out_gemm_mma(const float* __restrict__ bo, float* __restrict__ out)
{
    __shared__ __align__(16) __half Asm[3][4096];    // 128 rows x 32 k / stage
    __shared__ __align__(16) __half Bsm[3][4096];    // 128 cols x 32 k / stage

    GDC_WAIT();

    int t = threadIdx.x;
    int lane = t & 31, warp = t >> 5;
    int g = lane >> 2, tigL = lane & 3;
    int rb = blockIdx.y, jb = blockIdx.x;
    int wr = warp >> 2, wc = warp & 3;   // 2 row-groups (64) x 4 col-groups (32)

    float cf[4][4][4];
#pragma unroll
    for (int mt = 0; mt < 4; mt++)
#pragma unroll
        for (int nt = 0; nt < 4; nt++)
#pragma unroll
            for (int r = 0; r < 4; r++) cf[mt][nt][r] = 0.f;

#define STAGE(st, kc)                                                          \
    _Pragma("unroll")                                                          \
    for (int i = t; i < 512; i += 256) {                                       \
        int rt = i >> 6, kkl = (i >> 5) & 1, ln = i & 31;                      \
        cpa16(&Asm[st][i * 8],                                                 \
              g_ctxh + (((rb * 8 + rt) * 64 + (kc) * 2 + kkl) * 32 + ln) * 8); \
    }                                                                          \
    _Pragma("unroll")                                                          \
    for (int i = t; i < 512; i += 256) {                                       \
        int nt = i >> 5, kkb = (i >> 4) & 1, lp = i & 15;                      \
        cpa16(&Bsm[st][i * 8],                                                 \
              g_woh + (((jb * 16 + nt) * 64 + (kc) * 2 + kkb) * 32 + lp * 2) * 4); \
    }

    STAGE(0, 0); CPA_COMMIT();
    STAGE(1, 1); CPA_COMMIT();

#pragma unroll 1
    for (int c = 0; c < 32; c++) {
        CPA_WAIT1();
        __syncthreads();
        if (c + 2 < 32) { STAGE((c + 2) % 3, c + 2); }
        CPA_COMMIT();
        int b = c % 3;

#pragma unroll
        for (int kkl = 0; kkl < 2; kkl++) {
            uint4 av[4];
#pragma unroll
            for (int mt = 0; mt < 4; mt++)
                av[mt] = *(const uint4*)&Asm[b][(((wr * 4 + mt) * 2 + kkl) * 32 + lane) * 8];
#pragma unroll
            for (int nt = 0; nt < 4; nt++) {
                uint2 bv = *(const uint2*)&Bsm[b][(((wc * 4 + nt) * 2 + kkl) * 32 + lane) * 4];
#pragma unroll
                for (int mt = 0; mt < 4; mt++)
                    mma16(cf[mt][nt], av[mt].x, av[mt].y, av[mt].z, av[mt].w,
                          bv.x, bv.y);
            }
        }
    }

#pragma unroll
    for (int mt = 0; mt < 4; mt++) {
        int row = rb * 128 + wr * 64 + mt * 16 + g;
#pragma unroll
        for (int nt = 0; nt < 4; nt++) {
            int col = jb * 128 + wc * 32 + nt * 8 + 2 * tigL;
            float b0 = bo[col], b1 = bo[col + 1];
            float2 w0 = make_float2(cf[mt][nt][0] + b0, cf[mt][nt][1] + b1);
            float2 w1 = make_float2(cf[mt][nt][2] + b0, cf[mt][nt][3] + b1);
            *(float2*)&out[row * EMB + col]       = w0;
            *(float2*)&out[(row + 8) * EMB + col] = w1;
        }
    }
}

// ---------------------------------------------------------------------------
extern "C" void kernel_launch(void* const* d_in, const int* in_sizes, int n_in,
                              void* d_out, int out_size)
{
    const float* values = (const float*)d_in[0];
    const float* keys   = (const float*)d_in[1];
    const float* query  = (const float*)d_in[2];
    const int*   mask   = (const int*)d_in[3];
    const float* Wv     = (const float*)d_in[4];
    const float* Wk     = (const float*)d_in[5];
    const float* Wq     = (const float*)d_in[6];
    const float* Wo     = (const float*)d_in[7];
    const float* bo     = (const float*)d_in[8];
    float* out = (float*)d_out;

    // 1) projections (triggers dependents immediately)
    dim3 pgrid(NB * NH, LSEQ / 128, 3);
    proj_mma<<<pgrid, 128>>>(query, keys, values, Wq, Wk, Wv);

    // 2) round_wo: PSS -> overlaps proj (reads only harness input Wo)
    {
        cudaLaunchConfig_t cfg = {};
        cfg.gridDim  = dim3(EMB * EMB / 1024);
        cfg.blockDim = dim3(256);
        cudaLaunchAttribute at[1];
        at[0].id = cudaLaunchAttributeProgrammaticStreamSerialization;
        at[0].val.programmaticStreamSerializationAllowed = 1;
        cfg.attrs = at;
        cfg.numAttrs = 1;
        cudaLaunchKernelEx(&cfg, round_wo, Wo);
    }

    // 3) attention: 128 query rows per CTA (R10 config)
    dim3 agrid(NB * NH, LSEQ / BM);
    attn_mma<<<agrid, BM>>>(mask);

    // 4) output GEMM: PSS + device-side griddepcontrol.wait
    {
        cudaLaunchConfig_t cfg = {};
        cfg.gridDim  = dim3(EMB / 128, (NB * LSEQ) / 128);
        cfg.blockDim = dim3(256);
        cudaLaunchAttribute at[1];
        at[0].id = cudaLaunchAttributeProgrammaticStreamSerialization;
        at[0].val.programmaticStreamSerializationAllowed = 1;
        cfg.attrs = at;
        cfg.numAttrs = 1;
        cudaLaunchKernelEx(&cfg, out_gemm_mma, bo, out);
    }
}